// round 15
// baseline (speedup 1.0000x reference)
#include <cuda_runtime.h>
#include <cuda_bf16.h>
#include <cuda_fp16.h>
#include <cstdint>

#define SEQ    400
#define NHEADS 10
#define DK     64
#define NROWS  25600
#define DIM    640
#define CHUNK  (SEQ*DK)
#define NCHUNK ((NROWS/SEQ)*NHEADS)  // 640

// exp(s*0.125) = 2^(s*0.125*log2e); folded into Wq at convert time
#define QSCALE 0.180336878f

// Scratch (static __device__ arrays: the sanctioned no-alloc workaround)
__device__ __half g_Yh[(size_t)NROWS * DIM];   // f16 intermediate Y
__device__ __half g_Xh[(size_t)NROWS * DIM];   // f16 X for GEMM
__device__ __half g_Wh[(size_t)3 * DIM * DIM]; // f16 W for GEMM
__device__ __half g_Qh[(size_t)NROWS * DIM];
__device__ __half g_Kh[(size_t)NROWS * DIM];
__device__ __half g_Vh[(size_t)NROWS * DIM];

// ---------------------------------------------------------------------------
// helpers
// ---------------------------------------------------------------------------
__device__ __forceinline__ uint32_t smem_u32(const void* p) {
    uint32_t a;
    asm("{ .reg .u64 t; cvta.to.shared.u64 t, %1; cvt.u32.u64 %0, t; }" : "=r"(a) : "l"(p));
    return a;
}
#define SWZ128(o) ((o) ^ (((o) >> 3) & 0x70))

__device__ __forceinline__ void cp_async16(uint32_t dst, const void* src) {
    asm volatile("cp.async.cg.shared.global [%0], [%1], 16;" :: "r"(dst), "l"(src));
}
#define CP_COMMIT() asm volatile("cp.async.commit_group;" ::: "memory")
#define CP_WAIT(n)  asm volatile("cp.async.wait_group %0;" :: "n"(n) : "memory")

__device__ __forceinline__ void ldsm_x4(uint32_t* r, uint32_t addr) {
    asm volatile("ldmatrix.sync.aligned.m8n8.x4.shared.b16 {%0,%1,%2,%3}, [%4];"
                 : "=r"(r[0]), "=r"(r[1]), "=r"(r[2]), "=r"(r[3]) : "r"(addr));
}
__device__ __forceinline__ void ldsm_x4_t(uint32_t* r, uint32_t addr) {
    asm volatile("ldmatrix.sync.aligned.m8n8.x4.trans.shared.b16 {%0,%1,%2,%3}, [%4];"
                 : "=r"(r[0]), "=r"(r[1]), "=r"(r[2]), "=r"(r[3]) : "r"(addr));
}
// f16 inputs, f16 accum (packed D: c0 = row qr, c1 = row qr+8)
__device__ __forceinline__ void mma_16816hh(uint32_t* c, const uint32_t* a,
                                            uint32_t b0, uint32_t b1) {
    asm volatile("mma.sync.aligned.m16n8k16.row.col.f16.f16.f16.f16 "
                 "{%0,%1}, {%2,%3,%4,%5}, {%6,%7}, {%0,%1};"
                 : "+r"(c[0]), "+r"(c[1])
                 : "r"(a[0]), "r"(a[1]), "r"(a[2]), "r"(a[3]), "r"(b0), "r"(b1));
}
__device__ __forceinline__ uint32_t ex2h2(uint32_t h) {
    uint32_t r;
    asm("ex2.approx.f16x2 %0, %1;" : "=r"(r) : "r"(h));
    return r;
}

// ---------------------------------------------------------------------------
// fused fp32 -> f16 converts: x then Wq/Wk/Wv (one launch)
// ---------------------------------------------------------------------------
__global__ __launch_bounds__(256) void cvt_all(const float* __restrict__ x,
                                               const float* __restrict__ Wq,
                                               const float* __restrict__ Wk,
                                               const float* __restrict__ Wv) {
    const size_t XB = 8000;
    const size_t WB = 200;
    size_t b = blockIdx.x;
    const float* src;
    __half* dst;
    float sc = 1.0f;
    size_t i;
    if (b < XB) {
        i = (b * 256 + threadIdx.x) * 8;
        src = x; dst = g_Xh;
    } else {
        size_t wb = b - XB;
        int z = (int)(wb / WB);
        i = ((wb - (size_t)z * WB) * 256 + threadIdx.x) * 8;
        src = (z == 0) ? Wq : (z == 1) ? Wk : Wv;
        dst = g_Wh + (size_t)z * DIM * DIM;
        if (z == 0) sc = QSCALE;
    }
    float4 f0 = *(const float4*)(src + i);
    float4 f1 = *(const float4*)(src + i + 4);
    __half2 p0 = __floats2half2_rn(f0.x * sc, f0.y * sc);
    __half2 p1 = __floats2half2_rn(f0.z * sc, f0.w * sc);
    __half2 p2 = __floats2half2_rn(f1.x * sc, f1.y * sc);
    __half2 p3 = __floats2half2_rn(f1.z * sc, f1.w * sc);
    uint4 o;
    o.x = *(uint32_t*)&p0; o.y = *(uint32_t*)&p1;
    o.z = *(uint32_t*)&p2; o.w = *(uint32_t*)&p3;
    *(uint4*)(dst + i) = o;
}

// ---------------------------------------------------------------------------
// QKV GEMM via mma.sync (HMMA f16, f16 accum -> 2x rate) -> f16 Q/K/V.
// CTA tile 128x128, BK=64, 8 warps 4x2. 3-stage cp.async pipeline. 96KB smem.
// ---------------------------------------------------------------------------
#define GEMM_SMEM (3 * 32768)

__global__ __launch_bounds__(256, 2) void qkv_mma() {
    extern __shared__ char smem[];
    const int tid  = threadIdx.x;
    const int lane = tid & 31;
    const int wid  = tid >> 5;
    const int wm   = wid & 3;
    const int wn   = wid >> 2;
    const int z    = blockIdx.z;
    const int n0   = blockIdx.x * 128;
    const int m0   = blockIdx.y * 128;
    const __half* Xpt = g_Xh + (size_t)n0 * DIM;
    const __half* Wpt = g_Wh + (size_t)z * DIM * DIM + (size_t)m0 * DIM;
    const uint32_t sbase = smem_u32(smem);

    const int lr = tid >> 3;
    const int lcc = tid & 7;

    uint32_t acc[2][8][2];
#pragma unroll
    for (int i = 0; i < 2; ++i)
#pragma unroll
        for (int j = 0; j < 8; ++j) { acc[i][j][0] = 0u; acc[i][j][1] = 0u; }

    auto issue = [&](int c, int b) {
        const __half* xs = Xpt + c * 64;
        const __half* ws = Wpt + c * 64;
        const uint32_t stg = sbase + b * 32768;
#pragma unroll
        for (int i = 0; i < 4; ++i) {
            int r = lr + i * 32;
            uint32_t off = SWZ128(r * 128 + lcc * 16);
            cp_async16(stg + off, xs + (size_t)r * DIM + lcc * 8);
            cp_async16(stg + 16384 + off, ws + (size_t)r * DIM + lcc * 8);
        }
        CP_COMMIT();
    };

    issue(0, 0);
    issue(1, 1);

    const int arow = lane & 15;
    const int akb  = (lane >> 4) * 16;
    const int brow = (lane & 7) + ((lane >> 4) << 3);
    const int bkb  = ((lane >> 3) & 1) * 16;

    for (int c = 0; c < 10; ++c) {
        if (c == 9) { CP_WAIT(0); } else { CP_WAIT(1); }
        __syncthreads();
        if (c < 8) issue(c + 2, (c + 2) % 3);

        const uint32_t stg = sbase + (c % 3) * 32768;
        const uint32_t xb = stg;
        const uint32_t wb = stg + 16384;
#pragma unroll
        for (int ks = 0; ks < 4; ++ks) {
            uint32_t a[2][4];
#pragma unroll
            for (int i = 0; i < 2; ++i)
                ldsm_x4(a[i], xb + SWZ128((wm * 32 + i * 16 + arow) * 128 + ks * 32 + akb));
            uint32_t bf[4][4];
#pragma unroll
            for (int j = 0; j < 4; ++j)
                ldsm_x4(bf[j], wb + SWZ128((wn * 64 + j * 16 + brow) * 128 + ks * 32 + bkb));
#pragma unroll
            for (int i = 0; i < 2; ++i)
#pragma unroll
                for (int jj = 0; jj < 8; ++jj)
                    mma_16816hh(acc[i][jj], a[i], bf[jj >> 1][(jj & 1) * 2],
                                bf[jj >> 1][(jj & 1) * 2 + 1]);
        }
    }

    const int qr = lane >> 2;
    const int qc = (lane & 3) * 2;
    __half* Cz = (z == 0) ? g_Qh : (z == 1) ? g_Kh : g_Vh;
#pragma unroll
    for (int i = 0; i < 2; ++i)
#pragma unroll
        for (int jj = 0; jj < 8; ++jj) {
            int n = n0 + wm * 32 + i * 16 + qr;
            int m = m0 + wn * 64 + jj * 8 + qc;
            *(uint32_t*)&Cz[(size_t)n * DIM + m]       = acc[i][jj][0];
            *(uint32_t*)&Cz[(size_t)(n + 8) * DIM + m] = acc[i][jj][1];
        }
}

// ---------------------------------------------------------------------------
// FlashAttention-style attention via mma.sync, v10 (unchanged from R14):
//  - m32 per warp: 2 q-tiles share every K/V ldmatrix
//  - PV fused per nn-block; all f16 HMMA; ex2.approx.f16x2 on packed S frags
//  - 25 tiles = 12 pairs + 1 single; items 0..12 over grid(640,2) x 8 warps
// ---------------------------------------------------------------------------
#define VOFF2 52224                  // 51*1024, 1024-aligned
#define ATT_SMEM (VOFF2 + 51200)     // 103424

__global__ __launch_bounds__(256, 2) void attn_mma(const float* __restrict__ x)
{
    extern __shared__ char sm[];
    const int tid  = threadIdx.x;
    const int lane = tid & 31;
    const int w    = tid >> 5;
    const int chunk = blockIdx.x;
    const int half  = blockIdx.y;
    const size_t base = (size_t)chunk * CHUNK;
    const uint32_t KS = smem_u32(sm);
    const uint32_t VS = KS + VOFF2;

    // stage Km (raw-reshape layout [d][j], 816B padded rows) and V f16 (SW128)
    {
        const uint4* Kg = (const uint4*)(g_Kh + base);
        const uint4* Vg = (const uint4*)(g_Vh + base);
        for (int i = tid; i < 3200; i += 256) {
            int d = i / 50;
            int j = (i - d * 50) * 8;
            cp_async16(KS + d * 816 + j * 2, Kg + i);
            int row = i >> 3, cc = i & 7;
            cp_async16(VS + SWZ128(row * 128 + cc * 16), Vg + i);
        }
        CP_COMMIT();
        CP_WAIT(0);
    }
    __syncthreads();

    const int item = half * 7 + w;     // 0..12 valid (13 items: 12 pairs + 1)
    if (item > 12) return;
    const bool two = (item < 12);

    const int qr  = lane >> 2;
    const int l3  = lane & 3;
    const int l15 = lane & 15;
    const int lhi = lane >> 4;
    const uint32_t* Qg = (const uint32_t*)(g_Qh + base);

    const int q0 = item * 32;

    uint32_t aq0[4][4], aq1[4][4];
    {
        const int r0 = (q0 + qr) * 32;
        const int r1 = r0 + 8 * 32;
#pragma unroll
        for (int kt = 0; kt < 4; ++kt) {
            aq0[kt][0] = Qg[r0 + kt * 8 + l3];
            aq0[kt][1] = Qg[r1 + kt * 8 + l3];
            aq0[kt][2] = Qg[r0 + kt * 8 + l3 + 4];
            aq0[kt][3] = Qg[r1 + kt * 8 + l3 + 4];
        }
        if (two) {
            const int r2 = r0 + 16 * 32;
            const int r3 = r2 + 8 * 32;
#pragma unroll
            for (int kt = 0; kt < 4; ++kt) {
                aq1[kt][0] = Qg[r2 + kt * 8 + l3];
                aq1[kt][1] = Qg[r3 + kt * 8 + l3];
                aq1[kt][2] = Qg[r2 + kt * 8 + l3 + 4];
                aq1[kt][3] = Qg[r3 + kt * 8 + l3 + 4];
            }
        }
    }

    float l00 = 0.f, l01 = 0.f, l10 = 0.f, l11 = 0.f;
    uint32_t oh0[16], oh1[16];
#pragma unroll
    for (int n = 0; n < 16; ++n) { oh0[n] = 0u; oh1[n] = 0u; }

#pragma unroll
    for (int jc = 0; jc < 5; ++jc) {
        const int j0 = jc * 80;
        __half2 sa0 = __floats2half2_rn(0.f, 0.f);
        __half2 sb0 = sa0, sa1 = sa0, sb1 = sa0;

#pragma unroll
        for (int nn = 0; nn < 5; ++nn) {
            uint32_t s00[2] = {0u, 0u}, s01[2] = {0u, 0u};
            uint32_t s10[2] = {0u, 0u}, s11[2] = {0u, 0u};
#pragma unroll
            for (int kt = 0; kt < 4; ++kt) {
                uint32_t bk[4];
                ldsm_x4_t(bk, KS + (kt * 16 + l15) * 816 +
                              (j0 + nn * 16 + lhi * 8) * 2);
                mma_16816hh(s00, aq0[kt], bk[0], bk[1]);
                mma_16816hh(s01, aq0[kt], bk[2], bk[3]);
                if (two) {
                    mma_16816hh(s10, aq1[kt], bk[0], bk[1]);
                    mma_16816hh(s11, aq1[kt], bk[2], bk[3]);
                }
            }
            uint32_t A0[4], A1[4];
            A0[0] = ex2h2(s00[0]); A0[1] = ex2h2(s00[1]);
            A0[2] = ex2h2(s01[0]); A0[3] = ex2h2(s01[1]);
            sa0 = __hadd2(sa0, __hadd2(*(__half2*)&A0[0], *(__half2*)&A0[2]));
            sb0 = __hadd2(sb0, __hadd2(*(__half2*)&A0[1], *(__half2*)&A0[3]));
            if (two) {
                A1[0] = ex2h2(s10[0]); A1[1] = ex2h2(s10[1]);
                A1[2] = ex2h2(s11[0]); A1[3] = ex2h2(s11[1]);
                sa1 = __hadd2(sa1, __hadd2(*(__half2*)&A1[0], *(__half2*)&A1[2]));
                sb1 = __hadd2(sb1, __hadd2(*(__half2*)&A1[1], *(__half2*)&A1[3]));
            }
            const int krow = j0 + nn * 16 + l15;
#pragma unroll
            for (int dd = 0; dd < 4; ++dd) {
                uint32_t bv[4];
                ldsm_x4_t(bv, VS + SWZ128(krow * 128 + dd * 32 + lhi * 16));
                mma_16816hh(&oh0[4 * dd],     A0, bv[0], bv[1]);
                mma_16816hh(&oh0[4 * dd + 2], A0, bv[2], bv[3]);
                if (two) {
                    mma_16816hh(&oh1[4 * dd],     A1, bv[0], bv[1]);
                    mma_16816hh(&oh1[4 * dd + 2], A1, bv[2], bv[3]);
                }
            }
        }
        float2 fa = __half22float2(sa0);
        float2 fb = __half22float2(sb0);
        l00 += fa.x + fa.y;
        l01 += fb.x + fb.y;
        if (two) {
            float2 fc = __half22float2(sa1);
            float2 fd = __half22float2(sb1);
            l10 += fc.x + fc.y;
            l11 += fd.x + fd.y;
        }
    }

    l00 += __shfl_xor_sync(0xffffffffu, l00, 1);
    l00 += __shfl_xor_sync(0xffffffffu, l00, 2);
    l01 += __shfl_xor_sync(0xffffffffu, l01, 1);
    l01 += __shfl_xor_sync(0xffffffffu, l01, 2);
    l10 += __shfl_xor_sync(0xffffffffu, l10, 1);
    l10 += __shfl_xor_sync(0xffffffffu, l10, 2);
    l11 += __shfl_xor_sync(0xffffffffu, l11, 1);
    l11 += __shfl_xor_sync(0xffffffffu, l11, 2);

    const float i00 = 1.f / l00;
    const float i01 = 1.f / l01;
#pragma unroll
    for (int n = 0; n < 8; ++n) {
        int q = q0 + qr;
        int d = n * 8 + l3 * 2;
        size_t idx = base + (size_t)q * 64 + d;
        float2 xr = *(const float2*)&x[idx];
        float2 oc0 = __half22float2(*(__half2*)&oh0[2 * n]);
        __half2 y0 = __floats2half2_rn(oc0.x * i00 + xr.x, oc0.y * i00 + xr.y);
        *(uint32_t*)&g_Yh[idx] = *(uint32_t*)&y0;
        size_t idx2 = idx + 8 * 64;
        float2 xr2 = *(const float2*)&x[idx2];
        float2 oc1 = __half22float2(*(__half2*)&oh0[2 * n + 1]);
        __half2 y1 = __floats2half2_rn(oc1.x * i01 + xr2.x, oc1.y * i01 + xr2.y);
        *(uint32_t*)&g_Yh[idx2] = *(uint32_t*)&y1;
    }
    if (two) {
        const float i10 = 1.f / l10;
        const float i11 = 1.f / l11;
#pragma unroll
        for (int n = 0; n < 8; ++n) {
            int q = q0 + 16 + qr;
            int d = n * 8 + l3 * 2;
            size_t idx = base + (size_t)q * 64 + d;
            float2 xr = *(const float2*)&x[idx];
            float2 oc0 = __half22float2(*(__half2*)&oh1[2 * n]);
            __half2 y0 = __floats2half2_rn(oc0.x * i10 + xr.x, oc0.y * i10 + xr.y);
            *(uint32_t*)&g_Yh[idx] = *(uint32_t*)&y0;
            size_t idx2 = idx + 8 * 64;
            float2 xr2 = *(const float2*)&x[idx2];
            float2 oc1 = __half22float2(*(__half2*)&oh1[2 * n + 1]);
            __half2 y1 = __floats2half2_rn(oc1.x * i11 + xr2.x, oc1.y * i11 + xr2.y);
            *(uint32_t*)&g_Yh[idx2] = *(uint32_t*)&y1;
        }
    }
}

// ---------------------------------------------------------------------------
// LayerNorm: one warp per row, f16 input, fp32 output
// ---------------------------------------------------------------------------
__global__ __launch_bounds__(256) void ln_kernel(
    const float* __restrict__ gamma,
    const float* __restrict__ beta,
    float* __restrict__ out)
{
    const int lane = threadIdx.x & 31;
    const int w    = threadIdx.x >> 5;
    const int row  = blockIdx.x * 8 + w;
    const uint2* y = (const uint2*)(g_Yh + (size_t)row * DIM);

    float4 v[5];
    float s = 0.f, sq = 0.f;
#pragma unroll
    for (int u = 0; u < 5; ++u) {
        uint2 raw = y[lane + 32 * u];
        float2 a = __half22float2(*(__half2*)&raw.x);
        float2 b = __half22float2(*(__half2*)&raw.y);
        v[u] = make_float4(a.x, a.y, b.x, b.y);
        s  += v[u].x + v[u].y + v[u].z + v[u].w;
        sq += v[u].x * v[u].x + v[u].y * v[u].y + v[u].z * v[u].z + v[u].w * v[u].w;
    }
#pragma unroll
    for (int o = 16; o > 0; o >>= 1) {
        s  += __shfl_xor_sync(0xffffffffu, s, o);
        sq += __shfl_xor_sync(0xffffffffu, sq, o);
    }
    const float mu  = s * (1.f / DIM);
    float var = sq * (1.f / DIM) - mu * mu;
    var = fmaxf(var, 0.f);
    const float rinv = rsqrtf(var + 1e-5f);

    float* orow = out + (size_t)row * DIM;
#pragma unroll
    for (int u = 0; u < 5; ++u) {
        float4 g4 = ((const float4*)gamma)[lane + 32 * u];
        float4 b4 = ((const float4*)beta)[lane + 32 * u];
        float4 o;
        o.x = (v[u].x - mu) * rinv * g4.x + b4.x;
        o.y = (v[u].y - mu) * rinv * g4.y + b4.y;
        o.z = (v[u].z - mu) * rinv * g4.z + b4.z;
        o.w = (v[u].w - mu) * rinv * g4.w + b4.w;
        ((float4*)orow)[lane + 32 * u] = o;
    }
}

// ---------------------------------------------------------------------------
extern "C" void kernel_launch(void* const* d_in, const int* in_sizes, int n_in,
                              void* d_out, int out_size)
{
    const float* x     = (const float*)d_in[0];
    const float* Wq    = (const float*)d_in[1];
    const float* Wk    = (const float*)d_in[2];
    const float* Wv    = (const float*)d_in[3];
    const float* gamma = (const float*)d_in[4];
    const float* beta  = (const float*)d_in[5];
    float* out = (float*)d_out;

    cudaFuncSetAttribute(qkv_mma, cudaFuncAttributeMaxDynamicSharedMemorySize, GEMM_SMEM);
    cudaFuncSetAttribute(attn_mma, cudaFuncAttributeMaxDynamicSharedMemorySize, ATT_SMEM);

    cvt_all<<<8600, 256>>>(x, Wq, Wk, Wv);

    dim3 ggrid(NROWS / 128, DIM / 128, 3);
    qkv_mma<<<ggrid, 256, GEMM_SMEM>>>();

    dim3 agrid(NCHUNK, 2);
    attn_mma<<<agrid, 256, ATT_SMEM>>>(x);

    ln_kernel<<<NROWS / 8, 256>>>(gamma, beta, out);
}